// round 3
// baseline (speedup 1.0000x reference)
#include <cuda_runtime.h>

// out[b, j1*64 + j2] = x[b, 0, j1] * x[b, 1, j2]
// x: [32768, 2, 64] f32, out: [32768, 4096] f32
// 4 batch rows per CTA; 256 threads; each thread writes 16x float4 (64 floats)
// via streaming (evict-first) stores, interleaved across rows for store MLP.

#define N_MF    64
#define ROW_IN  128   // 2 * 64 floats per batch row
#define ROW_OUT 4096
#define ROWS_PER_CTA 4

__global__ void __launch_bounds__(256, 8)
anfis_outer_kernel(const float* __restrict__ x, float* __restrict__ out) {
    const int b0  = blockIdx.x * ROWS_PER_CTA;
    const int tid = threadIdx.x;

    // [row][half][64]: half 0 = x[b,0,:], half 1 = x[b,1,:]
    __shared__ float s[ROWS_PER_CTA][2][N_MF];

    // Load 4*128 = 512 floats with 256 threads: float2 each, coalesced burst.
    {
        const float2* __restrict__ x2 =
            reinterpret_cast<const float2*>(x + (size_t)b0 * ROW_IN);
        reinterpret_cast<float2*>(&s[0][0][0])[tid] = __ldg(&x2[tid]);
    }
    __syncthreads();

    const int tid4 = tid * 4;

    // Interleave: for each quarter k, store that quarter for ALL rows
    // (16 independent STG.128 per k-group start → deep store MLP).
    #pragma unroll
    for (int k = 0; k < 4; ++k) {
        const int idx = k * 1024 + tid4;      // linear output index in a row
        const int j1  = idx >> 6;             // 0..63
        const int j2  = idx & 63;             // multiple of 4
        #pragma unroll
        for (int r = 0; r < ROWS_PER_CTA; ++r) {
            const float  av = s[r][0][j1];
            const float4 bv = *reinterpret_cast<const float4*>(&s[r][1][j2]);
            float4 v;
            v.x = av * bv.x;
            v.y = av * bv.y;
            v.z = av * bv.z;
            v.w = av * bv.w;
            float4* __restrict__ o4 =
                reinterpret_cast<float4*>(out + (size_t)(b0 + r) * ROW_OUT);
            __stcs(&o4[idx >> 2], v);         // streaming: evict-first in L2
        }
    }
}

extern "C" void kernel_launch(void* const* d_in, const int* in_sizes, int n_in,
                              void* d_out, int out_size) {
    const float* x = (const float*)d_in[0];
    float* out = (float*)d_out;
    const int batch = in_sizes[0] / ROW_IN;              // 32768
    anfis_outer_kernel<<<batch / ROWS_PER_CTA, 256>>>(x, out);
}